// round 9
// baseline (speedup 1.0000x reference)
#include <cuda_runtime.h>

#define NF  256
#define GS  16
#define NG  16
#define HWS 3136        // 56*56
#define MB  32
#define NTOT (MB*HWS)   // 100352
#define NPAIR 136       // 16*17/2
#define NF2  (HWS/2)    // 1568 float2 positions
#define NF4  (HWS/4)    // 784  float4 positions
#define SS   4          // spatial split for stats (wave smoothing)
#define CH2  (NF2/SS)   // 392 float2 positions per stats chunk

typedef unsigned long long u64;

// Scratch (device globals: no allocation allowed). g_sig starts zeroed at
// module load; solve_kernel re-zeroes it after consuming -> every graph
// replay sees zeros without a dedicated zero kernel.
__device__ float g_sig[NG][152];      // 136 gram pairs + 16 channel sums (atomic)
__device__ float g_W[NG][NPAIR];      // lower-tri inv(chol(Sigma)), k = i*(i+1)/2 + j
__device__ float g_b[NG][GS];         // b_i = sum_{j<=i} W_ij * mu_j

// ---------------------------------------------------------------------------
// packed f32x2 helpers
// ---------------------------------------------------------------------------
__device__ __forceinline__ u64 ffma2(u64 a, u64 b, u64 c) {
    u64 d;
    asm("fma.rn.f32x2 %0, %1, %2, %3;" : "=l"(d) : "l"(a), "l"(b), "l"(c));
    return d;
}
__device__ __forceinline__ float2 u2f2(u64 v) {
    float2 f;
    asm("mov.b64 {%0, %1}, %2;" : "=f"(f.x), "=f"(f.y) : "l"(v));
    return f;
}

// ---------------------------------------------------------------------------
// Kernel 1: per-group raw Gram + channel sums, quarter-block decomposition,
// z-split over 4 spatial chunks. Grid (16,32,4), 320 threads = 10 warps.
// Explicit next-iteration prefetch: the 4-8 LDG.64 of iteration k+1 are in
// flight while the FFMA2 block of iteration k executes.
// ---------------------------------------------------------------------------
template<int QI, int QJ>
__device__ __forceinline__ void qb_body(u64* acc, float* s,
                                        const u64* va, const u64* vb) {
    constexpr bool DIAG = (QI == QJ);
    if (DIAG) {
        int k = 0;
#pragma unroll
        for (int a = 0; a < 4; a++) {
#pragma unroll
            for (int b = 0; b <= a; b++) { acc[k] = ffma2(va[a], va[b], acc[k]); k++; }
            float2 t = u2f2(va[a]);
            s[a] += t.x + t.y;
        }
    } else {
#pragma unroll
        for (int a = 0; a < 4; a++)
#pragma unroll
            for (int b = 0; b < 4; b++)
                acc[a * 4 + b] = ffma2(va[a], vb[b], acc[a * 4 + b]);
    }
}

template<int QI, int QJ>
__device__ __forceinline__ void qb_warp(const float* __restrict__ base,
                                        int lane, int f0, int g) {
    constexpr bool DIAG = (QI == QJ);
    constexpr int NACC = DIAG ? 10 : 16;

    u64 acc[NACC];
#pragma unroll
    for (int k = 0; k < NACC; k++) acc[k] = 0ull;
    float s[4];
#pragma unroll
    for (int c = 0; c < 4; c++) s[c] = 0.f;

    const int f1 = f0 + CH2;
    int f = f0 + lane;

    u64 va[4], vb[4];
#pragma unroll
    for (int a = 0; a < 4; a++)
        va[a] = ((const u64*)(base + (size_t)(4 * QI + a) * HWS))[f];
    if (!DIAG)
#pragma unroll
        for (int b = 0; b < 4; b++)
            vb[b] = ((const u64*)(base + (size_t)(4 * QJ + b) * HWS))[f];

    for (f += 32; f < f1; f += 32) {
        u64 na[4], nb[4];
#pragma unroll
        for (int a = 0; a < 4; a++)
            na[a] = ((const u64*)(base + (size_t)(4 * QI + a) * HWS))[f];
        if (!DIAG)
#pragma unroll
            for (int b = 0; b < 4; b++)
                nb[b] = ((const u64*)(base + (size_t)(4 * QJ + b) * HWS))[f];

        qb_body<QI, QJ>(acc, s, va, vb);

#pragma unroll
        for (int a = 0; a < 4; a++) va[a] = na[a];
        if (!DIAG)
#pragma unroll
            for (int b = 0; b < 4; b++) vb[b] = nb[b];
    }
    qb_body<QI, QJ>(acc, s, va, vb);

    // warp-reduce, then one atomic per entry
    static const int DA[10] = {0,1,1,2,2,2,3,3,3,3};
    static const int DB[10] = {0,0,1,0,1,2,0,1,2,3};
#pragma unroll
    for (int t = 0; t < NACC; t++) {
        float2 p = u2f2(acc[t]);
        float v = p.x + p.y;
#pragma unroll
        for (int sh = 16; sh > 0; sh >>= 1)
            v += __shfl_xor_sync(0xFFFFFFFFu, v, sh);
        if (lane == 0) {
            const int a = DIAG ? DA[t] : (t >> 2);
            const int b = DIAG ? DB[t] : (t & 3);
            const int i = 4 * QI + a;
            const int j = 4 * QJ + b;
            atomicAdd(&g_sig[g][i * (i + 1) / 2 + j], v);
        }
    }
    if (DIAG) {
#pragma unroll
        for (int c = 0; c < 4; c++) {
            float v = s[c];
#pragma unroll
            for (int sh = 16; sh > 0; sh >>= 1)
                v += __shfl_xor_sync(0xFFFFFFFFu, v, sh);
            if (lane == 0) atomicAdd(&g_sig[g][136 + 4 * QI + c], v);
        }
    }
}

__global__ __launch_bounds__(320, 2) void stats_kernel(const float* __restrict__ x) {
    const int g = blockIdx.x;
    const int m = blockIdx.y;
    const int z = blockIdx.z;
    const float* base = x + ((size_t)m * NF + (size_t)g * GS) * HWS;
    const int wid  = threadIdx.x >> 5;
    const int lane = threadIdx.x & 31;
    const int f0 = z * CH2;
    switch (wid) {
        case 0: qb_warp<0,0>(base, lane, f0, g); break;
        case 1: qb_warp<1,0>(base, lane, f0, g); break;
        case 2: qb_warp<1,1>(base, lane, f0, g); break;
        case 3: qb_warp<2,0>(base, lane, f0, g); break;
        case 4: qb_warp<2,1>(base, lane, f0, g); break;
        case 5: qb_warp<2,2>(base, lane, f0, g); break;
        case 6: qb_warp<3,0>(base, lane, f0, g); break;
        case 7: qb_warp<3,1>(base, lane, f0, g); break;
        case 8: qb_warp<3,2>(base, lane, f0, g); break;
        case 9: qb_warp<3,3>(base, lane, f0, g); break;
    }
}

// ---------------------------------------------------------------------------
// Kernel 2: g_sig -> sigma -> Cholesky -> inverse -> (W, b), then re-zero
// g_sig for the next graph replay. One warp per group (512 threads), fp32.
// ---------------------------------------------------------------------------
__global__ __launch_bounds__(512) void solve_kernel() {
    __shared__ float a [NG][GS][GS + 1];
    __shared__ float w [NG][GS][GS + 1];
    __shared__ float mu[NG][GS];
    __shared__ float red[NG][152];

    const int g    = threadIdx.x >> 5;
    const int lane = threadIdx.x & 31;
    const float n = (float)NTOT;

    for (int e = lane; e < 152; e += 32) {
        red[g][e] = g_sig[g][e];
        g_sig[g][e] = 0.f;          // restore replay invariant
    }
    __syncwarp();

    if (lane < GS) mu[g][lane] = red[g][136 + lane] / n;
    __syncwarp();

    for (int idx = lane; idx < 256; idx += 32) {
        const int i = idx >> 4, j = idx & 15;
        const int ii = i > j ? i : j;
        const int jj = i > j ? j : i;
        float G = red[g][ii * (ii + 1) / 2 + jj];
        float sh = (G - n * mu[g][i] * mu[g][j]) / (n - 1.0f);
        a[g][i][j] = (1.0f - 1e-6f) * sh + ((i == j) ? 1e-6f : 0.0f);
    }
    __syncwarp();

    // Cholesky in-place (lower), lane i owns row i
    for (int j = 0; j < GS; j++) {
        if (lane == j) a[g][j][j] = sqrtf(a[g][j][j]);
        __syncwarp();
        const float tjj = a[g][j][j];
        if (lane > j && lane < GS) a[g][lane][j] /= tjj;
        __syncwarp();
        if (lane > j && lane < GS) {
            const float lij = a[g][lane][j];
            for (int k = j + 1; k <= lane; k++)
                a[g][lane][k] -= lij * a[g][k][j];
        }
        __syncwarp();
    }

    // W = T^{-1}: lane j computes column j by forward substitution
    if (lane < GS) {
        const int j = lane;
        w[g][j][j] = 1.0f / a[g][j][j];
        for (int i = j + 1; i < GS; i++) {
            float s = 0.f;
            for (int k = j; k < i; k++) s += a[g][i][k] * w[g][k][j];
            w[g][i][j] = -s / a[g][i][i];
        }
        for (int i = j; i < GS; i++)
            g_W[g][i * (i + 1) / 2 + j] = w[g][i][j];
    }
    __syncwarp();

    if (lane < GS) {
        const int i = lane;
        float b = 0.f;
        for (int j = 0; j <= i; j++) b += w[g][i][j] * mu[g][j];
        g_b[g][i] = b;
    }
}

// ---------------------------------------------------------------------------
// Kernel 3: y = W*x - b (triangular). EXACT R2 measured-best config:
// grid (16,32), 128 threads, buffered v[16]/y[16] float4 (high ILP,
// 248 regs, 2 blocks/SM) -> 37.4us measured.
// ---------------------------------------------------------------------------
__global__ __launch_bounds__(128) void whiten_kernel(const float* __restrict__ x,
                                                     float* __restrict__ out) {
    const int g = blockIdx.x;
    const int m = blockIdx.y;

    __shared__ float sW[NPAIR];
    __shared__ float sb[GS];
    for (int i = threadIdx.x; i < NPAIR + GS; i += 128) {
        if (i < NPAIR) sW[i] = g_W[g][i];
        else           sb[i - NPAIR] = g_b[g][i - NPAIR];
    }
    __syncthreads();

    const size_t base = ((size_t)m * NF + (size_t)g * GS) * HWS;

    for (int f = threadIdx.x; f < NF4; f += 128) {
        float4 v[GS];
#pragma unroll
        for (int c = 0; c < GS; c++)
            v[c] = ((const float4*)(x + base + (size_t)c * HWS))[f];

        float4 y[GS];
#pragma unroll
        for (int i = 0; i < GS; i++) {
            const float b = sb[i];
            y[i].x = -b; y[i].y = -b; y[i].z = -b; y[i].w = -b;
#pragma unroll
            for (int j = 0; j <= i; j++) {
                const float w = sW[i * (i + 1) / 2 + j];
                y[i].x = fmaf(w, v[j].x, y[i].x);
                y[i].y = fmaf(w, v[j].y, y[i].y);
                y[i].z = fmaf(w, v[j].z, y[i].z);
                y[i].w = fmaf(w, v[j].w, y[i].w);
            }
        }

#pragma unroll
        for (int c = 0; c < GS; c++)
            ((float4*)(out + base + (size_t)c * HWS))[f] = y[c];
    }
}

// ---------------------------------------------------------------------------
extern "C" void kernel_launch(void* const* d_in, const int* in_sizes, int n_in,
                              void* d_out, int out_size) {
    const float* x = (const float*)d_in[0];
    float* out = (float*)d_out;

    dim3 sgrid(NG, MB, SS);
    stats_kernel<<<sgrid, 320>>>(x);
    solve_kernel<<<1, 512>>>();
    dim3 wgrid(NG, MB);
    whiten_kernel<<<wgrid, 128>>>(x, out);
}

// round 10
// speedup vs baseline: 1.1974x; 1.1974x over previous
#include <cuda_runtime.h>

#define NF  256
#define GS  16
#define NG  16
#define HWS 3136        // 56*56
#define MB  32
#define NTOT (MB*HWS)   // 100352
#define NPAIR 136       // 16*17/2
#define NF2  (HWS/2)    // 1568 float2 positions
#define NF4  (HWS/4)    // 784  float4 positions
#define SS   4          // spatial split for stats (wave smoothing)
#define CH2  (NF2/SS)   // 392 float2 positions per stats chunk
#define NBLK (MB*SS)    // 128 stats blocks per group

typedef unsigned long long u64;

// Scratch (device globals: no allocation allowed). g_sig / g_cnt start
// zeroed at module load; the last stats block per group re-zeroes them
// after the in-kernel solve -> every graph replay sees zeros.
__device__ float g_sig[NG][152];      // 136 gram pairs + 16 channel sums (atomic)
__device__ int   g_cnt[NG];           // per-group completion counter
__device__ float g_W[NG][NPAIR];      // lower-tri inv(chol(Sigma)), k = i*(i+1)/2 + j
__device__ float g_b[NG][GS];         // b_i = sum_{j<=i} W_ij * mu_j

// ---------------------------------------------------------------------------
// packed f32x2 helpers
// ---------------------------------------------------------------------------
__device__ __forceinline__ u64 ffma2(u64 a, u64 b, u64 c) {
    u64 d;
    asm("fma.rn.f32x2 %0, %1, %2, %3;" : "=l"(d) : "l"(a), "l"(b), "l"(c));
    return d;
}
__device__ __forceinline__ float2 u2f2(u64 v) {
    float2 f;
    asm("mov.b64 {%0, %1}, %2;" : "=f"(f.x), "=f"(f.y) : "l"(v));
    return f;
}

// ---------------------------------------------------------------------------
// Single-warp solve for one group: g_sig -> sigma -> Cholesky -> T^{-1} ->
// (W, b). Runs in the LAST stats block of each group (cold path).
// Reads g_sig with __ldcg (L2) since producers wrote via L2 atomics.
// ---------------------------------------------------------------------------
__device__ void solve_group(int g, int lane) {
    __shared__ float a [GS][GS + 1];
    __shared__ float w [GS][GS + 1];
    __shared__ float mu[GS];
    __shared__ float red[152];

    const float n = (float)NTOT;

    for (int e = lane; e < 152; e += 32) red[e] = __ldcg(&g_sig[g][e]);
    __syncwarp();

    if (lane < GS) mu[lane] = red[136 + lane] / n;
    __syncwarp();

    for (int idx = lane; idx < 256; idx += 32) {
        const int i = idx >> 4, j = idx & 15;
        const int ii = i > j ? i : j;
        const int jj = i > j ? j : i;
        float G = red[ii * (ii + 1) / 2 + jj];
        float sh = (G - n * mu[i] * mu[j]) / (n - 1.0f);
        a[i][j] = (1.0f - 1e-6f) * sh + ((i == j) ? 1e-6f : 0.0f);
    }
    __syncwarp();

    // Cholesky in-place (lower), lane i owns row i
    for (int j = 0; j < GS; j++) {
        if (lane == j) a[j][j] = sqrtf(a[j][j]);
        __syncwarp();
        const float tjj = a[j][j];
        if (lane > j && lane < GS) a[lane][j] /= tjj;
        __syncwarp();
        if (lane > j && lane < GS) {
            const float lij = a[lane][j];
            for (int k = j + 1; k <= lane; k++)
                a[lane][k] -= lij * a[k][j];
        }
        __syncwarp();
    }

    // W = T^{-1}: lane j computes column j by forward substitution
    if (lane < GS) {
        const int j = lane;
        w[j][j] = 1.0f / a[j][j];
        for (int i = j + 1; i < GS; i++) {
            float s = 0.f;
            for (int k = j; k < i; k++) s += a[i][k] * w[k][j];
            w[i][j] = -s / a[i][i];
        }
        for (int i = j; i < GS; i++)
            g_W[g][i * (i + 1) / 2 + j] = w[i][j];
    }
    __syncwarp();

    if (lane < GS) {
        const int i = lane;
        float b = 0.f;
        for (int j = 0; j <= i; j++) b += w[i][j] * mu[j];
        g_b[g][i] = b;
    }

    // restore replay invariants (no more producers for this group)
    for (int e = lane; e < 152; e += 32) g_sig[g][e] = 0.f;
    if (lane == 0) g_cnt[g] = 0;
}

// ---------------------------------------------------------------------------
// Kernel 1: per-group raw Gram + channel sums, quarter-block decomposition,
// z-split over 4 spatial chunks. Grid (16,32,4), 320 threads = 10 warps.
// EXACT R6 hot loop (measured 39.1us). Last block per group runs the solve.
// ---------------------------------------------------------------------------
template<int QI, int QJ>
__device__ __forceinline__ void qb_warp(const float* __restrict__ base,
                                        int lane, int f0, int g) {
    constexpr bool DIAG = (QI == QJ);
    constexpr int NACC = DIAG ? 10 : 16;

    u64 acc[NACC];
#pragma unroll
    for (int k = 0; k < NACC; k++) acc[k] = 0ull;
    float s[4];
#pragma unroll
    for (int c = 0; c < 4; c++) s[c] = 0.f;

    const int f1 = f0 + CH2;
    for (int f = f0 + lane; f < f1; f += 32) {   // ~12.25 iterations
        u64 va[4];
#pragma unroll
        for (int a = 0; a < 4; a++)
            va[a] = ((const u64*)(base + (size_t)(4 * QI + a) * HWS))[f];
        if (DIAG) {
            int k = 0;
#pragma unroll
            for (int a = 0; a < 4; a++) {
#pragma unroll
                for (int b = 0; b <= a; b++) { acc[k] = ffma2(va[a], va[b], acc[k]); k++; }
                float2 t = u2f2(va[a]);
                s[a] += t.x + t.y;
            }
        } else {
            u64 vb[4];
#pragma unroll
            for (int b = 0; b < 4; b++)
                vb[b] = ((const u64*)(base + (size_t)(4 * QJ + b) * HWS))[f];
#pragma unroll
            for (int a = 0; a < 4; a++)
#pragma unroll
                for (int b = 0; b < 4; b++)
                    acc[a * 4 + b] = ffma2(va[a], vb[b], acc[a * 4 + b]);
        }
    }

    // warp-reduce, then one atomic per entry
    static const int DA[10] = {0,1,1,2,2,2,3,3,3,3};
    static const int DB[10] = {0,0,1,0,1,2,0,1,2,3};
#pragma unroll
    for (int t = 0; t < NACC; t++) {
        float2 p = u2f2(acc[t]);
        float v = p.x + p.y;
#pragma unroll
        for (int sh = 16; sh > 0; sh >>= 1)
            v += __shfl_xor_sync(0xFFFFFFFFu, v, sh);
        if (lane == 0) {
            const int a = DIAG ? DA[t] : (t >> 2);
            const int b = DIAG ? DB[t] : (t & 3);
            const int i = 4 * QI + a;
            const int j = 4 * QJ + b;
            atomicAdd(&g_sig[g][i * (i + 1) / 2 + j], v);
        }
    }
    if (DIAG) {
#pragma unroll
        for (int c = 0; c < 4; c++) {
            float v = s[c];
#pragma unroll
            for (int sh = 16; sh > 0; sh >>= 1)
                v += __shfl_xor_sync(0xFFFFFFFFu, v, sh);
            if (lane == 0) atomicAdd(&g_sig[g][136 + 4 * QI + c], v);
        }
    }
}

__global__ __launch_bounds__(320, 3) void stats_kernel(const float* __restrict__ x) {
    const int g = blockIdx.x;
    const int m = blockIdx.y;
    const int z = blockIdx.z;
    const float* base = x + ((size_t)m * NF + (size_t)g * GS) * HWS;
    const int wid  = threadIdx.x >> 5;
    const int lane = threadIdx.x & 31;
    const int f0 = z * CH2;
    switch (wid) {
        case 0: qb_warp<0,0>(base, lane, f0, g); break;
        case 1: qb_warp<1,0>(base, lane, f0, g); break;
        case 2: qb_warp<1,1>(base, lane, f0, g); break;
        case 3: qb_warp<2,0>(base, lane, f0, g); break;
        case 4: qb_warp<2,1>(base, lane, f0, g); break;
        case 5: qb_warp<2,2>(base, lane, f0, g); break;
        case 6: qb_warp<3,0>(base, lane, f0, g); break;
        case 7: qb_warp<3,1>(base, lane, f0, g); break;
        case 8: qb_warp<3,2>(base, lane, f0, g); break;
        case 9: qb_warp<3,3>(base, lane, f0, g); break;
    }

    // last-block-per-group: release own atomics, count arrivals, solve.
    __threadfence();
    __syncthreads();
    __shared__ int is_last;
    if (threadIdx.x == 0)
        is_last = (atomicAdd(&g_cnt[g], 1) == NBLK - 1);
    __syncthreads();
    if (is_last && threadIdx.x < 32) {
        __threadfence();           // acquire: see all groups' g_sig atomics
        solve_group(g, lane);
    }
}

// ---------------------------------------------------------------------------
// Kernel 2: y = W*x - b (triangular). EXACT R2 measured-best config:
// grid (16,32), 128 threads, buffered v[16]/y[16] float4 -> 37.4us measured.
// ---------------------------------------------------------------------------
__global__ __launch_bounds__(128) void whiten_kernel(const float* __restrict__ x,
                                                     float* __restrict__ out) {
    const int g = blockIdx.x;
    const int m = blockIdx.y;

    __shared__ float sW[NPAIR];
    __shared__ float sb[GS];
    for (int i = threadIdx.x; i < NPAIR + GS; i += 128) {
        if (i < NPAIR) sW[i] = g_W[g][i];
        else           sb[i - NPAIR] = g_b[g][i - NPAIR];
    }
    __syncthreads();

    const size_t base = ((size_t)m * NF + (size_t)g * GS) * HWS;

    for (int f = threadIdx.x; f < NF4; f += 128) {
        float4 v[GS];
#pragma unroll
        for (int c = 0; c < GS; c++)
            v[c] = ((const float4*)(x + base + (size_t)c * HWS))[f];

        float4 y[GS];
#pragma unroll
        for (int i = 0; i < GS; i++) {
            const float b = sb[i];
            y[i].x = -b; y[i].y = -b; y[i].z = -b; y[i].w = -b;
#pragma unroll
            for (int j = 0; j <= i; j++) {
                const float w = sW[i * (i + 1) / 2 + j];
                y[i].x = fmaf(w, v[j].x, y[i].x);
                y[i].y = fmaf(w, v[j].y, y[i].y);
                y[i].z = fmaf(w, v[j].z, y[i].z);
                y[i].w = fmaf(w, v[j].w, y[i].w);
            }
        }

#pragma unroll
        for (int c = 0; c < GS; c++)
            ((float4*)(out + base + (size_t)c * HWS))[f] = y[c];
    }
}

// ---------------------------------------------------------------------------
extern "C" void kernel_launch(void* const* d_in, const int* in_sizes, int n_in,
                              void* d_out, int out_size) {
    const float* x = (const float*)d_in[0];
    float* out = (float*)d_out;

    dim3 sgrid(NG, MB, SS);
    stats_kernel<<<sgrid, 320>>>(x);
    dim3 wgrid(NG, MB);
    whiten_kernel<<<wgrid, 128>>>(x, out);
}